// round 2
// baseline (speedup 1.0000x reference)
#include <cuda_runtime.h>
#include <cstdint>

// ChannelDropout: out[b,c,t] = sig[b,c,t] * kept(b,c) / (eps + proba(b,c))
//   kept  = ||pos[b,c] - center|| > 0.2
//   proba = mean_j( ||pos[b,c] - mc[j]|| > 0.2 ),  j in [0,100)
//
// Shapes: B=64, C=273, T=3000.  One block per (b,c) channel.
// T*4 bytes = 12000 B = 750 float4 per channel, contiguous & coalesced.

#define CD_C      273
#define CD_T      3000
#define CD_NVEC   750          // T / 4
#define CD_NMC    100
#define CD_DROP   0.2f
#define CD_EPS    1e-8f

__global__ __launch_bounds__(256, 8)
void channel_dropout_kernel(const float4* __restrict__ sig,
                            const float*  __restrict__ pos,
                            const float*  __restrict__ center,
                            const float*  __restrict__ mc,
                            float4* __restrict__ out)
{
    const int bc = blockIdx.x;                 // 0 .. B*C-1

    // ---- per-channel scale (cheap, warp-redundant, hides under DRAM latency) ----
    const float px = pos[2 * bc + 0];
    const float py = pos[2 * bc + 1];
    const float cx = center[0];
    const float cy = center[1];

    // kept: distance from ban center (no FMA contraction -> match jax fp32)
    const float dx = px - cx;
    const float dy = py - cy;
    const float d2 = __fadd_rn(__fmul_rn(dx, dx), __fmul_rn(dy, dy));
    const float kept = (sqrtf(d2) > CD_DROP) ? 1.0f : 0.0f;

    // Monte-Carlo keep count: each lane of each warp handles 4 trials,
    // then butterfly-reduce within the warp (no shared mem, no bar.sync).
    const int lane = threadIdx.x & 31;
    int cnt = 0;
#pragma unroll
    for (int j = lane; j < CD_NMC; j += 32) {
        const float mx  = mc[2 * j + 0];
        const float my  = mc[2 * j + 1];
        const float ddx = px - mx;
        const float ddy = py - my;
        const float dd2 = __fadd_rn(__fmul_rn(ddx, ddx), __fmul_rn(ddy, ddy));
        cnt += (sqrtf(dd2) > CD_DROP) ? 1 : 0;
    }
#pragma unroll
    for (int off = 16; off > 0; off >>= 1)
        cnt += __shfl_xor_sync(0xffffffffu, cnt, off);

    const float proba = (float)cnt / (float)CD_NMC;
    const float scale = kept / (CD_EPS + proba);   // kept==0 -> exact 0 output

    // ---- stream 750 float4 of this channel ----
    const float4* __restrict__ s = sig + (size_t)bc * CD_NVEC;
    float4*       __restrict__ o = out + (size_t)bc * CD_NVEC;

    for (int i = threadIdx.x; i < CD_NVEC; i += 256) {
        float4 v = s[i];
        v.x *= scale;
        v.y *= scale;
        v.z *= scale;
        v.w *= scale;
        o[i] = v;
    }
}

extern "C" void kernel_launch(void* const* d_in, const int* in_sizes, int n_in,
                              void* d_out, int out_size)
{
    const float4* sig    = (const float4*)d_in[0];   // brain_sig  (B,C,T) fp32
    const float*  pos    = (const float*) d_in[1];   // positions  (B,C,2)
    const float*  center = (const float*) d_in[2];   // center     (2,)
    const float*  mc     = (const float*) d_in[3];   // mc_centers (100,2)
    float4*       out    = (float4*)d_out;

    const int BC = in_sizes[1] / 2;                  // B*C = 17472

    channel_dropout_kernel<<<BC, 256>>>(sig, pos, center, mc, out);
}